// round 8
// baseline (speedup 1.0000x reference)
#include <cuda_runtime.h>
#include <math.h>

// PMXELoss: NQ=4096 queries, NS=16384 supports, D=128, C=64
#define NQ_   4096
#define NS_   16384
#define D_    128
#define C_    64
#define INFV  1000.0f

#define NBLK  256              // one fused kernel: 256 blocks x 256 threads
#define QBLK  (NQ_ / NBLK)     // 16 queries per block (2 per warp)
#define CSB   64               // blocks 0..63 also compute one class each

// Static device scratch (no allocations allowed)
__device__ float4 g_mus4[C_ * 32];   // final per-class mu (float4 chunks)
__device__ float  g_ss[C_];          // per-class sum ||xs_j||^2
__device__ float  g_mn[C_];          // ||mu_c||^2
__device__ int    g_cnt[C_];         // per-class counts
__device__ float  g_bsum[NBLK];      // per-block partial loss sums
__device__ int    g_bar  = 0;        // grid barrier counter (self-resetting)
__device__ int    g_done = 0;        // final-reduction counter (self-resetting)

__device__ __forceinline__ float dot4(float4 a, float4 b) {
    return a.x * b.x + a.y * b.y + a.z * b.z + a.w * b.w;
}
__device__ __forceinline__ float fma4(float4 m, float4 v, float acc) {
    return fmaf(m.w, v.w, fmaf(m.z, v.z, fmaf(m.y, v.y, fmaf(m.x, v.x, acc))));
}

__global__ void __launch_bounds__(256, 2) k_fused(
    const float4* __restrict__ xq4, const int* __restrict__ yq,
    const float4* __restrict__ xs4, const int* __restrict__ ys,
    const int* __restrict__ pos, float* __restrict__ out)
{
    const int tid  = threadIdx.x;
    const int lane = tid & 31;
    const int w    = tid >> 5;          // warp 0..7
    const int grp  = lane >> 4;         // query-in-warp 0/1
    const int ds   = lane & 15;         // dim-split 0..15 (dims 8*ds .. 8*ds+7)
    const int q    = blockIdx.x * QBLK + w * 2 + grp;

    __shared__ float4 s_mu[C_ * 32];    // 32 KB, interleaved chunk layout
    __shared__ float  s_inv[C_], s_A[C_], s_B[C_], s_cntf[C_], s_mn[C_];
    __shared__ float4 s_acc[8][32];     // classsum block-combine
    __shared__ float  s_ssw[8];
    __shared__ int    s_cntw[8];
    __shared__ float  s_wsum[8];
    __shared__ float  s_f[NBLK];
    __shared__ int    s_last;

    // ---- phase 0: per-query loads (independent of class stats) ----
    float4 xr0 = xq4[q * 32 + 2 * ds];          // dims [8ds, 8ds+4)
    float4 xr1 = xq4[q * 32 + 2 * ds + 1];      // dims [8ds+4, 8ds+8)
    const int p   = pos[q];
    const int cq  = ys[p];
    const int yqi = yq[q];
    float4 sp0 = xs4[p * 32 + 2 * ds];
    float4 sp1 = xs4[p * 32 + 2 * ds + 1];

    // ---- phase 1 (blocks 0..63): full class-c statistics ----
    if (blockIdx.x < CSB) {
        const int c = blockIdx.x;
        float4 acc = make_float4(0.f, 0.f, 0.f, 0.f);
        float  ss  = 0.f;
        int    cnt = 0;

        const int rbase = w * (NS_ / 8);            // 2048 rows per warp
        const int4* ys4 = (const int4*)ys;
        const int ybase = rbase / 4;                // int4 index base
        int4 ybuf[4];
#pragma unroll
        for (int i = 0; i < 4; ++i) ybuf[i] = ys4[ybase + i * 32 + lane];

#pragma unroll
        for (int sc = 0; sc < 16; ++sc) {           // 16 superchunks of 128 rows
            int4 yv = ybuf[sc & 3];
            if (sc + 4 < 16) ybuf[sc & 3] = ys4[ybase + (sc + 4) * 32 + lane];
            int j0 = rbase + sc * 128;
            unsigned m0 = __ballot_sync(0xffffffffu, yv.x == c);
            unsigned m1 = __ballot_sync(0xffffffffu, yv.y == c);
            unsigned m2 = __ballot_sync(0xffffffffu, yv.z == c);
            unsigned m3 = __ballot_sync(0xffffffffu, yv.w == c);
            cnt += __popc(m0) + __popc(m1) + __popc(m2) + __popc(m3);
#pragma unroll
            for (int k = 0; k < 4; ++k) {           // component k -> rows j0+4b+k
                unsigned m = (k == 0) ? m0 : (k == 1) ? m1 : (k == 2) ? m2 : m3;
                while (m) {
                    int b = __ffs(m) - 1; m &= m - 1;
                    float4 vv = xs4[(j0 + 4 * b + k) * 32 + lane];  // 512B row
                    acc.x += vv.x; acc.y += vv.y; acc.z += vv.z; acc.w += vv.w;
                    ss = fma4(vv, vv, ss);
                }
            }
        }
        s_acc[w][lane] = acc;
#pragma unroll
        for (int o = 16; o; o >>= 1) ss += __shfl_xor_sync(0xffffffffu, ss, o);
        if (lane == 0) { s_ssw[w] = ss; s_cntw[w] = cnt; }   // cnt warp-uniform
        __syncthreads();

        if (w == 0) {
            float4 t = s_acc[0][lane];
#pragma unroll
            for (int ww = 1; ww < 8; ++ww) {
                float4 u = s_acc[ww][lane];
                t.x += u.x; t.y += u.y; t.z += u.z; t.w += u.w;
            }
            g_mus4[c * 32 + lane] = t;
            float mn = dot4(t, t);
#pragma unroll
            for (int o = 16; o; o >>= 1) mn += __shfl_xor_sync(0xffffffffu, mn, o);
            float sst = (lane < 8) ? s_ssw[lane] : 0.f;
            int   cnT = (lane < 8) ? s_cntw[lane] : 0;
#pragma unroll
            for (int o = 4; o; o >>= 1) {
                sst += __shfl_xor_sync(0xffffffffu, sst, o);
                cnT += __shfl_xor_sync(0xffffffffu, cnT, o);
            }
            if (lane == 0) { g_ss[c] = sst; g_cnt[c] = cnT; g_mn[c] = mn; }
        }
        __syncthreads();
    }

    // ---- grid barrier (all 256 blocks resident: launch_bounds(256,2)) ----
    if (tid == 0) {
        __threadfence();
        atomicAdd(&g_bar, 1);
        while (((volatile int*)&g_bar)[0] < NBLK) { }
        __threadfence();
    }
    __syncthreads();

    // ---- phase 2 prologue: stage mu + per-class params into shared ----
#pragma unroll
    for (int it = 0; it < 8; ++it) {
        int idx = tid + it * 256;                // 0..2047
        int c = idx >> 5, k = idx & 31;
        float4 v = __ldcg(&g_mus4[idx]);
        // interleave so lane ds reads consecutive float4s: chunk 2ds -> slot ds,
        // chunk 2ds+1 -> slot 16+ds
        s_mu[c * 32 + ((k & 1) << 4) + (k >> 1)] = v;
    }
    if (tid < C_) {
        float cn = (float)__ldcg(&g_cnt[tid]);
        float sv = __ldcg(&g_ss[tid]);
        float iv = 1.f / (cn - 1.f);
        s_cntf[tid] = cn;
        s_inv[tid]  = iv;
        s_A[tid]    = -0.5f * cn * iv;
        s_B[tid]    = -0.5f * sv * iv;
        s_mn[tid]   = __ldcg(&g_mn[tid]);
    }
    __syncthreads();

    // ---- hot loop: 64 class dots, 8 dims/thread, no shuffles ----
    float v[C_];
#pragma unroll
    for (int c = 0; c < C_; ++c) {
        float4 m0 = s_mu[c * 32 + ds];
        float4 m1 = s_mu[c * 32 + 16 + ds];
        v[c] = fma4(m1, xr1, fma4(m0, xr0, 0.f));
    }

    // ---- recursive-halving exchange: 60 shfl, lane ends with 4 full dots ----
#pragma unroll
    for (int s = 0; s < 4; ++s) {
        const int o = 1 << s;
        const int h = 32 >> s;                  // 32,16,8,4
        const bool up = (lane & o) != 0;
#pragma unroll
        for (int i = 0; i < h; ++i) {
            float send = up ? v[i] : v[i + h];
            float keep = up ? v[i + h] : v[i];
            v[i] = keep + __shfl_xor_sync(0xffffffffu, send, o);
        }
    }
    // lane (within 16-group) owns classes cls_base + j, j in 0..3
    const int l = ds;
    const int cls_base = ((l & 1) << 5) | ((l & 2) << 3) | ((l & 4) << 1) | ((l & 8) >> 1);

    // ---- per-query scalars (16-lane group reductions) ----
    float qq = dot4(xr0, xr0) + dot4(xr1, xr1);
    float pp = dot4(sp0, sp0) + dot4(sp1, sp1);
    float dp = dot4(xr0, sp0) + dot4(xr1, sp1);
#pragma unroll
    for (int o = 1; o <= 8; o <<= 1) {
        qq += __shfl_xor_sync(0xffffffffu, qq, o);
        pp += __shfl_xor_sync(0xffffffffu, pp, o);
        dp += __shfl_xor_sync(0xffffffffu, dp, o);
    }

    // normalized logits for owned classes; extract raw dot(x, mu_cq)
    float dm = 0.f;
    float nv[4];
#pragma unroll
    for (int j = 0; j < 4; ++j) {
        int c = cls_base + j;
        if (c == cq) dm = v[j];
        nv[j] = fmaf(v[j], s_inv[c], fmaf(s_A[c], qq, s_B[c]));
    }
#pragma unroll
    for (int o = 1; o <= 8; o <<= 1) dm += __shfl_xor_sync(0xffffffffu, dm, o);

    // exact (i, pos_i) pair logit + bucket patch
    float pair  = -0.5f * fmaxf(qq + pp - 2.f * dp, 0.f);
    float delta = ((s_cntf[yqi] > 1.5f) ? -INFV : 0.f) - pair;
#pragma unroll
    for (int j = 0; j < 4; ++j)
        if (cls_base + j == cq) nv[j] += delta * s_inv[cq];

    // analytic pos_logit: ||x - proto||^2 = (e^2 qq - 2 e dm + ||mu||^2)/den^2
    float den  = fmaxf(s_cntf[cq] - 1.f, 0.1f);
    float e    = den + 1.f;
    float d2   = (e * e * qq - 2.f * e * dm + s_mn[cq]) / (den * den);
    float plog = -sqrtf(fmaxf(d2, 0.f));

    // ---- LSE over 64 classes (4 local + group butterfly) ----
    float mx = fmaxf(fmaxf(nv[0], nv[1]), fmaxf(nv[2], nv[3]));
#pragma unroll
    for (int o = 1; o <= 8; o <<= 1)
        mx = fmaxf(mx, __shfl_xor_sync(0xffffffffu, mx, o));
    float ex = expf(nv[0] - mx) + expf(nv[1] - mx) + expf(nv[2] - mx) + expf(nv[3] - mx);
#pragma unroll
    for (int o = 1; o <= 8; o <<= 1)
        ex += __shfl_xor_sync(0xffffffffu, ex, o);
    float res = (mx + logf(ex)) - plog;

    // ---- fused mean: warp -> block -> last-block ----
    float t = (ds == 0) ? res : 0.f;
    t += __shfl_xor_sync(0xffffffffu, t, 16);   // combine the 2 group leaders
    if (lane == 0) s_wsum[w] = t;
    __syncthreads();

    if (tid == 0) {
        float s = 0.f;
#pragma unroll
        for (int i = 0; i < 8; ++i) s += s_wsum[i];
        g_bsum[blockIdx.x] = s;
        __threadfence();
        int old = atomicAdd(&g_done, 1);
        s_last = (old == NBLK - 1);
    }
    __syncthreads();
    if (s_last) {
        __threadfence();
        s_f[tid] = __ldcg(&g_bsum[tid]);        // NBLK == blockDim.x == 256
        __syncthreads();
#pragma unroll
        for (int o = NBLK / 2; o; o >>= 1) {
            if (tid < o) s_f[tid] += s_f[tid + o];
            __syncthreads();
        }
        if (tid == 0) {
            out[0]  = s_f[0] * (1.0f / (float)NQ_);
            g_done  = 0;                        // reset for next graph replay
            g_bar   = 0;
        }
    }
}

// ---------------------------------------------------------------------------
extern "C" void kernel_launch(void* const* d_in, const int* in_sizes, int n_in,
                              void* d_out, int out_size) {
    const float4* xq4 = (const float4*)d_in[0];   // [NQ, D] f32
    const int*    yqp = (const int*)   d_in[1];   // [NQ]    i32
    const float4* xs4 = (const float4*)d_in[2];   // [NS, D] f32
    const int*    ysp = (const int*)   d_in[3];   // [NS]    i32
    const int*    pop = (const int*)   d_in[4];   // [NQ]    i32
    (void)in_sizes; (void)n_in; (void)out_size;

    k_fused<<<NBLK, 256>>>(xq4, yqp, xs4, ysp, pop, (float*)d_out);
}

// round 9
// speedup vs baseline: 1.3050x; 1.3050x over previous
#include <cuda_runtime.h>
#include <math.h>

// PMXELoss: NQ=4096 queries, NS=16384 supports, D=128, C=64
#define NQ_   4096
#define NS_   16384
#define D_    128
#define C_    64
#define INFV  1000.0f

#define NBLK  256              // k_query blocks (16 queries each, 16 thr/query)
#define QBLK  (NQ_ / NBLK)     // 16
#define CSBLK 128              // k_classsum blocks (2 per class)

// Static device scratch (no allocations allowed)
__device__ float4 g_musp[CSBLK * 32];   // per-(class,half) partial mu
__device__ float  g_ssp[CSBLK];         // per-(class,half) partial sum ||xs||^2
__device__ int    g_cntp[CSBLK];        // per-(class,half) partial counts
__device__ float  g_bsum[NBLK];         // per-block partial loss sums
__device__ int    g_done = 0;           // last-block counter (self-resetting)

__device__ __forceinline__ float dot4(float4 a, float4 b) {
    return a.x * b.x + a.y * b.y + a.z * b.z + a.w * b.w;
}
__device__ __forceinline__ float fma4(float4 m, float4 v, float acc) {
    return fmaf(m.w, v.w, fmaf(m.z, v.z, fmaf(m.y, v.y, fmaf(m.x, v.x, acc))));
}

// ---------------------------------------------------------------------------
// 128 blocks x 1024 threads: block = (class c = bid>>1, half = bid&1).
// 32 warps x 256 rows each; ys read as int4 with both batches prefetched, so
// the ballot chain never stalls on label loads. Deterministic, atomic-free.
__global__ void __launch_bounds__(1024) k_classsum(const float4* __restrict__ xs4,
                                                   const int*    __restrict__ ys) {
    const int c    = blockIdx.x >> 1;
    const int half = blockIdx.x & 1;
    const int lane = threadIdx.x & 31;
    const int w    = threadIdx.x >> 5;          // 0..31

    __shared__ float4 s_acc[32][32];
    __shared__ float  s_ss[32];
    __shared__ int    s_cnt[32];

    const int base  = half * (NS_ / 2) + w * 256;   // 256 rows per warp
    const int4* ys4 = (const int4*)ys;
    const int ybase = base >> 2;
    int4 y0 = ys4[ybase + lane];                    // rows [base, base+128)
    int4 y1 = ys4[ybase + 32 + lane];               // rows [base+128, base+256)

    float4 acc = make_float4(0.f, 0.f, 0.f, 0.f);
    float  ss  = 0.f;
    int    cnt = 0;

#pragma unroll
    for (int sc = 0; sc < 2; ++sc) {
        int4 yv = sc ? y1 : y0;
        int  j0 = base + sc * 128;
        unsigned m0 = __ballot_sync(0xffffffffu, yv.x == c);
        unsigned m1 = __ballot_sync(0xffffffffu, yv.y == c);
        unsigned m2 = __ballot_sync(0xffffffffu, yv.z == c);
        unsigned m3 = __ballot_sync(0xffffffffu, yv.w == c);
        cnt += __popc(m0) + __popc(m1) + __popc(m2) + __popc(m3);
#pragma unroll
        for (int k = 0; k < 4; ++k) {               // component k -> row j0+4b+k
            unsigned m = (k == 0) ? m0 : (k == 1) ? m1 : (k == 2) ? m2 : m3;
            while (m) {
                int b = __ffs(m) - 1; m &= m - 1;
                float4 vv = xs4[(j0 + 4 * b + k) * 32 + lane];  // 512B row
                acc.x += vv.x; acc.y += vv.y; acc.z += vv.z; acc.w += vv.w;
                ss = fma4(vv, vv, ss);
            }
        }
    }
    s_acc[w][lane] = acc;
#pragma unroll
    for (int o = 16; o; o >>= 1) ss += __shfl_xor_sync(0xffffffffu, ss, o);
    if (lane == 0) { s_ss[w] = ss; s_cnt[w] = cnt; }   // cnt is warp-uniform
    __syncthreads();

    if (w == 0) {
        float4 t = s_acc[0][lane];
#pragma unroll
        for (int ww = 1; ww < 32; ++ww) {
            float4 u = s_acc[ww][lane];
            t.x += u.x; t.y += u.y; t.z += u.z; t.w += u.w;
        }
        g_musp[blockIdx.x * 32 + lane] = t;

        float sst = s_ss[lane];
        int   cn  = s_cnt[lane];
#pragma unroll
        for (int o = 16; o; o >>= 1) {
            sst += __shfl_xor_sync(0xffffffffu, sst, o);
            cn  += __shfl_xor_sync(0xffffffffu, cn, o);
        }
        if (lane == 0) { g_ssp[blockIdx.x] = sst; g_cntp[blockIdx.x] = cn; }
    }
}

// ---------------------------------------------------------------------------
// 256 blocks x 256 threads, 16 threads/query (2 queries/warp, 8 dims/thread).
// Hot loop: 64 class dots, all FMA from a staged smem mu tile (no shuffles).
// ||mu||^2 is computed inside the staging loop (class = warp + 8*it, chunk =
// lane) -> zero bank conflicts, 8 warp reductions. Epilogue: recursive-halving
// exchange (60 shfl), division-free normalized logits, analytic pos_logit,
// LSE, fused mean via last-block reduction.
__global__ void __launch_bounds__(256, 2) k_query(
    const float4* __restrict__ xq4, const int* __restrict__ yq,
    const float4* __restrict__ xs4, const int* __restrict__ ys,
    const int* __restrict__ pos, float* __restrict__ out)
{
    const int tid  = threadIdx.x;
    const int lane = tid & 31;
    const int w    = tid >> 5;          // warp 0..7
    const int grp  = lane >> 4;         // query-in-warp 0/1
    const int ds   = lane & 15;         // dim-split 0..15 (dims 8ds .. 8ds+7)
    const int q    = blockIdx.x * QBLK + w * 2 + grp;

    __shared__ float4 s_mu[C_ * 32];    // 32 KB, interleaved chunk layout
    __shared__ float  s_inv[C_], s_A[C_], s_B[C_], s_cntf[C_], s_mn[C_];
    __shared__ float  s_wsum[8];
    __shared__ float  s_f[NBLK];
    __shared__ int    s_last;

    // ---- per-query loads first (independent of class stats) ----
    float4 xr0 = xq4[q * 32 + 2 * ds];
    float4 xr1 = xq4[q * 32 + 2 * ds + 1];
    const int p   = pos[q];
    const int cq  = ys[p];
    const int yqi = yq[q];
    float4 sp0 = xs4[p * 32 + 2 * ds];
    float4 sp1 = xs4[p * 32 + 2 * ds + 1];

    // ---- stage mu (combining halves) + fused ||mu||^2 partials ----
    float mnp[8];
#pragma unroll
    for (int it = 0; it < 8; ++it) {
        int idx = tid + it * 256;               // c = w + 8*it, k = lane
        int c = idx >> 5, k = idx & 31;
        float4 a = __ldcg(&g_musp[(2 * c) * 32 + k]);
        float4 b = __ldcg(&g_musp[(2 * c + 1) * 32 + k]);
        a.x += b.x; a.y += b.y; a.z += b.z; a.w += b.w;
        // interleave: chunk 2ds -> slot ds, chunk 2ds+1 -> slot 16+ds
        s_mu[c * 32 + ((k & 1) << 4) + (k >> 1)] = a;
        mnp[it] = dot4(a, a);
    }
#pragma unroll
    for (int it = 0; it < 8; ++it) {
        float r = mnp[it];
#pragma unroll
        for (int o = 16; o; o >>= 1) r += __shfl_xor_sync(0xffffffffu, r, o);
        if (lane == 0) s_mn[w + 8 * it] = r;
    }
    if (tid < C_) {
        float cn = (float)(__ldcg(&g_cntp[2 * tid]) + __ldcg(&g_cntp[2 * tid + 1]));
        float sv = __ldcg(&g_ssp[2 * tid]) + __ldcg(&g_ssp[2 * tid + 1]);
        float iv = 1.f / (cn - 1.f);
        s_cntf[tid] = cn;
        s_inv[tid]  = iv;
        s_A[tid]    = -0.5f * cn * iv;
        s_B[tid]    = -0.5f * sv * iv;
    }
    __syncthreads();

    // ---- hot loop: 64 class dots, 8 dims/thread, no shuffles ----
    float v[C_];
#pragma unroll
    for (int c = 0; c < C_; ++c) {
        float4 m0 = s_mu[c * 32 + ds];
        float4 m1 = s_mu[c * 32 + 16 + ds];
        v[c] = fma4(m1, xr1, fma4(m0, xr0, 0.f));
    }

    // ---- recursive-halving exchange: 60 shfl, lane ends with 4 full dots ----
#pragma unroll
    for (int s = 0; s < 4; ++s) {
        const int o = 1 << s;
        const int h = 32 >> s;                  // 32,16,8,4
        const bool up = (lane & o) != 0;
#pragma unroll
        for (int i = 0; i < h; ++i) {
            float send = up ? v[i] : v[i + h];
            float keep = up ? v[i + h] : v[i];
            v[i] = keep + __shfl_xor_sync(0xffffffffu, send, o);
        }
    }
    // lane (within 16-group) owns classes cls_base + j, j in 0..3
    const int l = ds;
    const int cls_base = ((l & 1) << 5) | ((l & 2) << 3) | ((l & 4) << 1) | ((l & 8) >> 1);

    // ---- per-query scalars (16-lane group reductions) ----
    float qq = dot4(xr0, xr0) + dot4(xr1, xr1);
    float pp = dot4(sp0, sp0) + dot4(sp1, sp1);
    float dp = dot4(xr0, sp0) + dot4(xr1, sp1);
#pragma unroll
    for (int o = 1; o <= 8; o <<= 1) {
        qq += __shfl_xor_sync(0xffffffffu, qq, o);
        pp += __shfl_xor_sync(0xffffffffu, pp, o);
        dp += __shfl_xor_sync(0xffffffffu, dp, o);
    }

    // normalized logits for owned classes; extract raw dot(x, mu_cq)
    float dm = 0.f;
    float nv[4];
#pragma unroll
    for (int j = 0; j < 4; ++j) {
        int c = cls_base + j;
        if (c == cq) dm = v[j];
        nv[j] = fmaf(v[j], s_inv[c], fmaf(s_A[c], qq, s_B[c]));
    }
#pragma unroll
    for (int o = 1; o <= 8; o <<= 1) dm += __shfl_xor_sync(0xffffffffu, dm, o);

    // exact (i, pos_i) pair logit + bucket patch
    float pair  = -0.5f * fmaxf(qq + pp - 2.f * dp, 0.f);
    float delta = ((s_cntf[yqi] > 1.5f) ? -INFV : 0.f) - pair;
#pragma unroll
    for (int j = 0; j < 4; ++j)
        if (cls_base + j == cq) nv[j] += delta * s_inv[cq];

    // analytic pos_logit: ||x - proto||^2 = (e^2 qq - 2 e dm + ||mu||^2)/den^2
    float den  = fmaxf(s_cntf[cq] - 1.f, 0.1f);
    float e    = den + 1.f;
    float d2   = (e * e * qq - 2.f * e * dm + s_mn[cq]) / (den * den);
    float plog = -sqrtf(fmaxf(d2, 0.f));

    // ---- LSE over 64 classes (4 local + group butterfly) ----
    float mx = fmaxf(fmaxf(nv[0], nv[1]), fmaxf(nv[2], nv[3]));
#pragma unroll
    for (int o = 1; o <= 8; o <<= 1)
        mx = fmaxf(mx, __shfl_xor_sync(0xffffffffu, mx, o));
    float ex = expf(nv[0] - mx) + expf(nv[1] - mx) + expf(nv[2] - mx) + expf(nv[3] - mx);
#pragma unroll
    for (int o = 1; o <= 8; o <<= 1)
        ex += __shfl_xor_sync(0xffffffffu, ex, o);
    float res = (mx + logf(ex)) - plog;

    // ---- fused mean: warp -> block -> last-block ----
    float t = (ds == 0) ? res : 0.f;
    t += __shfl_xor_sync(0xffffffffu, t, 16);   // combine the 2 group leaders
    if (lane == 0) s_wsum[w] = t;
    __syncthreads();

    if (tid == 0) {
        float s = 0.f;
#pragma unroll
        for (int i = 0; i < 8; ++i) s += s_wsum[i];
        g_bsum[blockIdx.x] = s;
        __threadfence();
        int old = atomicAdd(&g_done, 1);
        s_last = (old == NBLK - 1);
    }
    __syncthreads();
    if (s_last) {
        __threadfence();
        s_f[tid] = __ldcg(&g_bsum[tid]);        // NBLK == blockDim.x == 256
        __syncthreads();
#pragma unroll
        for (int o = NBLK / 2; o; o >>= 1) {
            if (tid < o) s_f[tid] += s_f[tid + o];
            __syncthreads();
        }
        if (tid == 0) {
            out[0] = s_f[0] * (1.0f / (float)NQ_);
            g_done = 0;                         // reset for next graph replay
        }
    }
}

// ---------------------------------------------------------------------------
extern "C" void kernel_launch(void* const* d_in, const int* in_sizes, int n_in,
                              void* d_out, int out_size) {
    const float4* xq4 = (const float4*)d_in[0];   // [NQ, D] f32
    const int*    yqp = (const int*)   d_in[1];   // [NQ]    i32
    const float4* xs4 = (const float4*)d_in[2];   // [NS, D] f32
    const int*    ysp = (const int*)   d_in[3];   // [NS]    i32
    const int*    pop = (const int*)   d_in[4];   // [NQ]    i32
    (void)in_sizes; (void)n_in; (void)out_size;

    k_classsum<<<CSBLK, 1024>>>(xs4, ysp);
    k_query<<<NBLK, 256>>>(xq4, yqp, xs4, ysp, pop, (float*)d_out);
}

// round 10
// speedup vs baseline: 1.3226x; 1.0135x over previous
#include <cuda_runtime.h>
#include <math.h>

// PMXELoss: NQ=4096 queries, NS=16384 supports, D=128, C=64
#define NQ_   4096
#define NS_   16384
#define D_    128
#define C_    64
#define INFV  1000.0f

#define NBLK  512              // k_query blocks (8 queries each, 16 thr/query)
#define QBLK  (NQ_ / NBLK)     // 8

// Static device scratch (no allocations allowed)
__device__ float4 g_muI[C_ * 32];   // FINAL per-class mu, interleaved chunk layout
__device__ float  g_mn[C_];         // ||mu_c||^2
__device__ float  g_cntf[C_];       // per-class counts (float)
__device__ float  g_inv[C_];        // 1/(cnt-1)
__device__ float  g_A[C_];          // -0.5*cnt/(cnt-1)
__device__ float  g_B[C_];          // -0.5*SS/(cnt-1)
__device__ float  g_bsum[NBLK];     // per-block partial loss sums
__device__ int    g_done = 0;       // last-block counter (self-resetting)

__device__ __forceinline__ float dot4(float4 a, float4 b) {
    return a.x * b.x + a.y * b.y + a.z * b.z + a.w * b.w;
}
__device__ __forceinline__ float fma4(float4 m, float4 v, float acc) {
    return fmaf(m.w, v.w, fmaf(m.z, v.z, fmaf(m.y, v.y, fmaf(m.x, v.x, acc))));
}

// ---------------------------------------------------------------------------
// 64 blocks x 1024 threads: one block per class. 32 warps x 512 rows each,
// all y-labels prefetched as int4. Writes FINAL mu (interleaved layout) and
// all derived per-class parameters, so k_query has zero prologue work.
__global__ void __launch_bounds__(1024) k_classsum(const float4* __restrict__ xs4,
                                                   const int*    __restrict__ ys) {
    const int c    = blockIdx.x;
    const int lane = threadIdx.x & 31;
    const int w    = threadIdx.x >> 5;          // 0..31

    __shared__ float4 s_acc[32][32];
    __shared__ float  s_ss[32];
    __shared__ int    s_cnt[32];

    const int base  = w * 512;                  // 512 rows per warp
    const int4* ys4 = (const int4*)ys;
    const int ybase = base >> 2;
    int4 ybuf[4];
#pragma unroll
    for (int i = 0; i < 4; ++i) ybuf[i] = ys4[ybase + i * 32 + lane];

    float4 acc = make_float4(0.f, 0.f, 0.f, 0.f);
    float  ss  = 0.f;
    int    cnt = 0;

#pragma unroll
    for (int b = 0; b < 4; ++b) {
        int4 yv = ybuf[b];
        int  j0 = base + b * 128;
        unsigned m0 = __ballot_sync(0xffffffffu, yv.x == c);
        unsigned m1 = __ballot_sync(0xffffffffu, yv.y == c);
        unsigned m2 = __ballot_sync(0xffffffffu, yv.z == c);
        unsigned m3 = __ballot_sync(0xffffffffu, yv.w == c);
        cnt += __popc(m0) + __popc(m1) + __popc(m2) + __popc(m3);
#pragma unroll
        for (int k = 0; k < 4; ++k) {           // component k -> row j0+4*bit+k
            unsigned m = (k == 0) ? m0 : (k == 1) ? m1 : (k == 2) ? m2 : m3;
            while (m) {
                int bb = __ffs(m) - 1; m &= m - 1;
                float4 vv = xs4[(j0 + 4 * bb + k) * 32 + lane];  // 512B row
                acc.x += vv.x; acc.y += vv.y; acc.z += vv.z; acc.w += vv.w;
                ss = fma4(vv, vv, ss);
            }
        }
    }
    s_acc[w][lane] = acc;
#pragma unroll
    for (int o = 16; o; o >>= 1) ss += __shfl_xor_sync(0xffffffffu, ss, o);
    if (lane == 0) { s_ss[w] = ss; s_cnt[w] = cnt; }   // cnt is warp-uniform
    __syncthreads();

    if (w == 0) {
        float4 t = s_acc[0][lane];
#pragma unroll
        for (int ww = 1; ww < 32; ++ww) {
            float4 u = s_acc[ww][lane];
            t.x += u.x; t.y += u.y; t.z += u.z; t.w += u.w;
        }
        // interleaved layout: chunk k -> slot ((k&1)<<4) | (k>>1)
        g_muI[c * 32 + ((lane & 1) << 4) + (lane >> 1)] = t;

        float mn  = dot4(t, t);
        float sst = s_ss[lane];
        int   cn  = s_cnt[lane];
#pragma unroll
        for (int o = 16; o; o >>= 1) {
            mn  += __shfl_xor_sync(0xffffffffu, mn, o);
            sst += __shfl_xor_sync(0xffffffffu, sst, o);
            cn  += __shfl_xor_sync(0xffffffffu, cn, o);
        }
        if (lane == 0) {
            float cnf = (float)cn;
            float iv  = 1.f / (cnf - 1.f);
            g_mn[c]   = mn;
            g_cntf[c] = cnf;
            g_inv[c]  = iv;
            g_A[c]    = -0.5f * cnf * iv;
            g_B[c]    = -0.5f * sst * iv;
        }
    }
}

// ---------------------------------------------------------------------------
// 512 blocks x 128 threads, 16 threads/query (2 queries/warp, 8 dims/thread).
// mu is read directly through L1 (32KB tile stays hot per SM) -- no smem
// staging, no block barrier before the tail. Hot loop: 64 class dots, pure
// LDG.128 + FMA. Epilogue: recursive-halving exchange (60 shfl), division-free
// normalized logits, analytic pos_logit, LSE, fused mean.
__global__ void __launch_bounds__(128, 4) k_query(
    const float4* __restrict__ xq4, const int* __restrict__ yq,
    const float4* __restrict__ xs4, const int* __restrict__ ys,
    const int* __restrict__ pos, float* __restrict__ out)
{
    const int tid  = threadIdx.x;
    const int lane = tid & 31;
    const int w    = tid >> 5;          // warp 0..3
    const int grp  = lane >> 4;         // query-in-warp 0/1
    const int ds   = lane & 15;         // dim-split 0..15 (dims 8ds .. 8ds+7)
    const int q    = blockIdx.x * QBLK + w * 2 + grp;

    __shared__ float s_wsum[4];
    __shared__ float s_f[128];
    __shared__ int   s_last;

    // ---- per-query loads ----
    float4 xr0 = xq4[q * 32 + 2 * ds];
    float4 xr1 = xq4[q * 32 + 2 * ds + 1];
    const int p   = pos[q];
    const int cq  = ys[p];
    const int yqi = yq[q];
    float4 sp0 = xs4[p * 32 + 2 * ds];
    float4 sp1 = xs4[p * 32 + 2 * ds + 1];

    // ---- hot loop: 64 class dots, 8 dims/thread, L1-resident mu ----
    float v[C_];
#pragma unroll
    for (int c = 0; c < C_; ++c) {
        float4 m0 = __ldg(&g_muI[c * 32 + ds]);
        float4 m1 = __ldg(&g_muI[c * 32 + 16 + ds]);
        v[c] = fma4(m1, xr1, fma4(m0, xr0, 0.f));
    }

    // ---- recursive-halving exchange: 60 shfl, lane ends with 4 full dots ----
#pragma unroll
    for (int s = 0; s < 4; ++s) {
        const int o = 1 << s;
        const int h = 32 >> s;                  // 32,16,8,4
        const bool up = (lane & o) != 0;
#pragma unroll
        for (int i = 0; i < h; ++i) {
            float send = up ? v[i] : v[i + h];
            float keep = up ? v[i + h] : v[i];
            v[i] = keep + __shfl_xor_sync(0xffffffffu, send, o);
        }
    }
    // lane (within 16-group) owns classes cls_base + j, j in 0..3
    const int l = ds;
    const int cls_base = ((l & 1) << 5) | ((l & 2) << 3) | ((l & 4) << 1) | ((l & 8) >> 1);

    // ---- per-query scalars (16-lane group reductions) ----
    float qq = dot4(xr0, xr0) + dot4(xr1, xr1);
    float pp = dot4(sp0, sp0) + dot4(sp1, sp1);
    float dp = dot4(xr0, sp0) + dot4(xr1, sp1);
#pragma unroll
    for (int o = 1; o <= 8; o <<= 1) {
        qq += __shfl_xor_sync(0xffffffffu, qq, o);
        pp += __shfl_xor_sync(0xffffffffu, pp, o);
        dp += __shfl_xor_sync(0xffffffffu, dp, o);
    }

    // normalized logits for owned classes; extract raw dot(x, mu_cq)
    float dm = 0.f;
    float nv[4];
#pragma unroll
    for (int j = 0; j < 4; ++j) {
        int c = cls_base + j;
        if (c == cq) dm = v[j];
        nv[j] = fmaf(v[j], __ldg(&g_inv[c]),
                     fmaf(__ldg(&g_A[c]), qq, __ldg(&g_B[c])));
    }
#pragma unroll
    for (int o = 1; o <= 8; o <<= 1) dm += __shfl_xor_sync(0xffffffffu, dm, o);

    // exact (i, pos_i) pair logit + bucket patch
    float pair  = -0.5f * fmaxf(qq + pp - 2.f * dp, 0.f);
    float delta = ((__ldg(&g_cntf[yqi]) > 1.5f) ? -INFV : 0.f) - pair;
    const float invcq = __ldg(&g_inv[cq]);
#pragma unroll
    for (int j = 0; j < 4; ++j)
        if (cls_base + j == cq) nv[j] += delta * invcq;

    // analytic pos_logit: ||x - proto||^2 = (e^2 qq - 2 e dm + ||mu||^2)/den^2
    float cnq  = __ldg(&g_cntf[cq]);
    float den  = fmaxf(cnq - 1.f, 0.1f);
    float e    = den + 1.f;
    float d2   = (e * e * qq - 2.f * e * dm + __ldg(&g_mn[cq])) / (den * den);
    float plog = -sqrtf(fmaxf(d2, 0.f));

    // ---- LSE over 64 classes (4 local + group butterfly) ----
    float mx = fmaxf(fmaxf(nv[0], nv[1]), fmaxf(nv[2], nv[3]));
#pragma unroll
    for (int o = 1; o <= 8; o <<= 1)
        mx = fmaxf(mx, __shfl_xor_sync(0xffffffffu, mx, o));
    float ex = expf(nv[0] - mx) + expf(nv[1] - mx) + expf(nv[2] - mx) + expf(nv[3] - mx);
#pragma unroll
    for (int o = 1; o <= 8; o <<= 1)
        ex += __shfl_xor_sync(0xffffffffu, ex, o);
    float res = (mx + logf(ex)) - plog;

    // ---- fused mean: warp -> block -> last-block ----
    float t = (ds == 0) ? res : 0.f;
    t += __shfl_xor_sync(0xffffffffu, t, 16);   // combine the 2 group leaders
    if (lane == 0) s_wsum[w] = t;
    __syncthreads();

    if (tid == 0) {
        float s = s_wsum[0] + s_wsum[1] + s_wsum[2] + s_wsum[3];
        g_bsum[blockIdx.x] = s;
        __threadfence();
        int old = atomicAdd(&g_done, 1);
        s_last = (old == NBLK - 1);
    }
    __syncthreads();
    if (s_last) {
        __threadfence();
        float acc = 0.f;
#pragma unroll
        for (int i = 0; i < NBLK / 128; ++i) {
            float u;
            asm volatile("ld.global.cg.f32 %0, [%1];"
                         : "=f"(u) : "l"(&g_bsum[tid + i * 128]));
            acc += u;
        }
        s_f[tid] = acc;
        __syncthreads();
#pragma unroll
        for (int o = 64; o; o >>= 1) {
            if (tid < o) s_f[tid] += s_f[tid + o];
            __syncthreads();
        }
        if (tid == 0) {
            out[0] = s_f[0] * (1.0f / (float)NQ_);
            g_done = 0;                         // reset for next graph replay
        }
    }
}

// ---------------------------------------------------------------------------
extern "C" void kernel_launch(void* const* d_in, const int* in_sizes, int n_in,
                              void* d_out, int out_size) {
    const float4* xq4 = (const float4*)d_in[0];   // [NQ, D] f32
    const int*    yqp = (const int*)   d_in[1];   // [NQ]    i32
    const float4* xs4 = (const float4*)d_in[2];   // [NS, D] f32
    const int*    ysp = (const int*)   d_in[3];   // [NS]    i32
    const int*    pop = (const int*)   d_in[4];   // [NQ]    i32
    (void)in_sizes; (void)n_in; (void)out_size;

    k_classsum<<<C_, 1024>>>(xs4, ysp);
    k_query<<<NBLK, 128>>>(xq4, yqp, xs4, ysp, pop, (float*)d_out);
}